// round 2
// baseline (speedup 1.0000x reference)
#include <cuda_runtime.h>
#include <math.h>

#define BATCH 4
#define SEQ   4096
#define DM    1024
#define DK    64
#define TOK   (BATCH*SEQ)   // 16384 tokens total

// Scratch for projected q,k,v  (static device arrays: allocation-guard safe)
__device__ float g_q[TOK*DK];
__device__ float g_k[TOK*DK];
__device__ float g_v[TOK*DK];

// ---------------------------------------------------------------------------
// Kernel 1: fused QKV projection.  out[t,d] = sum_c x[t,c]*w[d,c] + bias[d]
// Grid: (TOK/64, 3). Block: 256 threads. 64 rows x 64 cols per block.
// ---------------------------------------------------------------------------
#define KT 32

__global__ __launch_bounds__(256) void qkv_kernel(
    const float* __restrict__ x,
    const float* __restrict__ wq, const float* __restrict__ bq,
    const float* __restrict__ wk, const float* __restrict__ bk,
    const float* __restrict__ wv, const float* __restrict__ bv)
{
    __shared__ float Ash[KT][68];   // [k][row], stride 68: float4-aligned, bank-spread
    __shared__ float Bsh[KT][68];   // [k][col d]

    const int m0  = blockIdx.x * 64;
    const int sel = blockIdx.y;
    const float* w    = (sel == 0) ? wq : (sel == 1) ? wk : wv;
    const float* bias = (sel == 0) ? bq : (sel == 1) ? bk : bv;
    float* out        = (sel == 0) ? g_q : (sel == 1) ? g_k : g_v;

    const int t  = threadIdx.x;
    const int tx = t & 15;          // col group
    const int ty = t >> 4;          // row group
    const int lk  = t & 31;         // k-within-tile for loads
    const int lr0 = t >> 5;         // 0..7

    float acc[4][4] = {};

    for (int k0 = 0; k0 < DM; k0 += KT) {
        __syncthreads();
        #pragma unroll
        for (int j = 0; j < 8; j++) {
            int r = lr0 + j * 8;
            Ash[lk][r] = x[(size_t)(m0 + r) * DM + k0 + lk];
        }
        #pragma unroll
        for (int j = 0; j < 8; j++) {
            int d = lr0 + j * 8;
            Bsh[lk][d] = w[(size_t)d * DM + k0 + lk];
        }
        __syncthreads();
        #pragma unroll
        for (int k = 0; k < KT; k++) {
            float4 a4 = *(const float4*)&Ash[k][ty * 4];
            float4 b4 = *(const float4*)&Bsh[k][tx * 4];
            float av[4] = {a4.x, a4.y, a4.z, a4.w};
            float bvv[4] = {b4.x, b4.y, b4.z, b4.w};
            #pragma unroll
            for (int i = 0; i < 4; i++)
                #pragma unroll
                for (int j = 0; j < 4; j++)
                    acc[i][j] += av[i] * bvv[j];
        }
    }

    float4 bb = *(const float4*)&bias[tx * 4];
    float bias4[4] = {bb.x, bb.y, bb.z, bb.w};
    #pragma unroll
    for (int i = 0; i < 4; i++) {
        int r = ty * 4 + i;
        float4 res;
        res.x = acc[i][0] + bias4[0];
        res.y = acc[i][1] + bias4[1];
        res.z = acc[i][2] + bias4[2];
        res.w = acc[i][3] + bias4[3];
        *(float4*)&out[(size_t)(m0 + r) * DK + tx * 4] = res;
    }
}

// ---------------------------------------------------------------------------
// Kernel 2: causal flash attention, fp32.
// Block = 256 threads = 64 q-rows x 4 "quad" threads per row.
// Thread (r, quad) owns S columns {quad + 4i} and O dims {quad + 4i}.
// Smem: Ksh[c][k] (stride 68), Vt[d][c] (stride 68); P aliases Ksh.
// ---------------------------------------------------------------------------

// Work schedule: all 256 CTAs co-resident (2/SM). SMs 108..147 host a single
// CTA -> give them the largest tiles; paired bids (s, s+148) sum to ~53 tiles.
__device__ __forceinline__ void sched(int bid, int& b, int& qt) {
    int r;
    if (bid >= 108 && bid < 148)      r = bid - 108;        // ranks 0..39 (largest)
    else if (bid < 108)               r = 40 + bid;         // ranks 40..147
    else                              r = 403 - bid;        // ranks 148..255 (smallest)
    b  = r & 3;
    qt = 63 - (r >> 2);
}

__global__ __launch_bounds__(256, 2) void attn_kernel(float* __restrict__ out)
{
    __shared__ float Ksh[64 * 68];   // K tile [c][k]; later aliased as P tile [r][c]
    __shared__ float Vt [64 * 68];   // V tile transposed [d][c]
    float* Psh = Ksh;

    int b, qt;
    sched(blockIdx.x, b, qt);

    const int t    = threadIdx.x;
    const int r    = t >> 2;     // q-row within tile (0..63)
    const int quad = t & 3;

    const int rowg = qt * 64 + r;
    const size_t qbase = ((size_t)b * SEQ + rowg) * DK;

    // Q row in registers, pre-scaled by 1/sqrt(64)
    float4 qreg[16];
    #pragma unroll
    for (int k4 = 0; k4 < 16; k4++) {
        float4 v = *(const float4*)&g_q[qbase + k4 * 4];
        v.x *= 0.125f; v.y *= 0.125f; v.z *= 0.125f; v.w *= 0.125f;
        qreg[k4] = v;
    }

    float o[16];
    #pragma unroll
    for (int i = 0; i < 16; i++) o[i] = 0.f;
    float m = -3.402823466e38f;
    float l = 0.f;

    for (int kt = 0; kt <= qt; kt++) {
        __syncthreads();   // previous PV done: safe to overwrite Ksh(=P) and Vt
        const size_t kvbase = ((size_t)b * SEQ + kt * 64) * DK;
        #pragma unroll
        for (int it = 0; it < 16; it++) {
            int idx = t + it * 256;           // 0..4095
            int c = idx >> 6, k = idx & 63;
            float kv = g_k[kvbase + idx];
            float vv = g_v[kvbase + idx];
            Ksh[c * 68 + k] = kv;
            Vt [k * 68 + c] = vv;             // k here is the head-dim d of V
        }
        __syncthreads();

        // S[r][cc] = q[r] . K[cc], cc = quad + 4i
        float s[16];
        #pragma unroll
        for (int i = 0; i < 16; i++) {
            const int cc = quad + 4 * i;
            const float4* kp = (const float4*)&Ksh[cc * 68];
            float acc = 0.f;
            #pragma unroll
            for (int k4 = 0; k4 < 16; k4++) {
                float4 kv = kp[k4];
                float4 qv = qreg[k4];
                acc += qv.x * kv.x + qv.y * kv.y + qv.z * kv.z + qv.w * kv.w;
            }
            s[i] = acc;
        }
        if (kt == qt) {
            #pragma unroll
            for (int i = 0; i < 16; i++)
                if (quad + 4 * i > r) s[i] = -3.402823466e38f;
        }

        // Online softmax stats (row shared by 4 quad lanes)
        float tmax = s[0];
        #pragma unroll
        for (int i = 1; i < 16; i++) tmax = fmaxf(tmax, s[i]);
        tmax = fmaxf(tmax, __shfl_xor_sync(0xffffffffu, tmax, 1));
        tmax = fmaxf(tmax, __shfl_xor_sync(0xffffffffu, tmax, 2));
        const float mnew  = fmaxf(m, tmax);
        const float scale = __expf(m - mnew);
        float tsum = 0.f;
        #pragma unroll
        for (int i = 0; i < 16; i++) {
            float p = __expf(s[i] - mnew);
            s[i] = p;
            tsum += p;
        }
        tsum += __shfl_xor_sync(0xffffffffu, tsum, 1);
        tsum += __shfl_xor_sync(0xffffffffu, tsum, 2);
        l = l * scale + tsum;
        m = mnew;
        #pragma unroll
        for (int i = 0; i < 16; i++) o[i] *= scale;

        __syncthreads();   // everyone done reading Ksh -> safe to write P over it
        #pragma unroll
        for (int i = 0; i < 16; i++)
            Psh[r * 68 + quad + 4 * i] = s[i];
        __syncthreads();   // P ready

        // O[r][d] += sum_c P[r][c] * V[c][d], d = quad + 4i, Vt[d][c]
        #pragma unroll
        for (int k4 = 0; k4 < 16; k4++) {
            float4 p = *(const float4*)&Psh[r * 68 + k4 * 4];
            #pragma unroll
            for (int i = 0; i < 16; i++) {
                const int d = quad + 4 * i;
                float4 vv = *(const float4*)&Vt[d * 68 + k4 * 4];
                o[i] += p.x * vv.x + p.y * vv.y + p.z * vv.z + p.w * vv.w;
            }
        }
    }

    const float linv = 1.f / l;
    #pragma unroll
    for (int i = 0; i < 16; i++)
        out[qbase + quad + 4 * i] = o[i] * linv;
}

// ---------------------------------------------------------------------------
extern "C" void kernel_launch(void* const* d_in, const int* in_sizes, int n_in,
                              void* d_out, int out_size) {
    (void)in_sizes; (void)n_in; (void)out_size;
    const float* x  = (const float*)d_in[0];
    const float* wq = (const float*)d_in[1];
    const float* bq = (const float*)d_in[2];
    const float* wk = (const float*)d_in[3];
    const float* bk = (const float*)d_in[4];
    const float* wv = (const float*)d_in[5];
    const float* bv = (const float*)d_in[6];
    float* out = (float*)d_out;

    qkv_kernel<<<dim3(TOK / 64, 3), 256>>>(x, wq, bq, wk, bk, wv, bv);
    attn_kernel<<<256, 256>>>(out);
}

// round 3
// speedup vs baseline: 2.4509x; 2.4509x over previous
#include <cuda_runtime.h>
#include <math.h>
#include <stdint.h>

#define BATCH 4
#define SEQ   4096
#define DM    1024
#define DK    64
#define TOK   (BATCH*SEQ)   // 16384 tokens total

// Scratch for projected q,k,v  (static device arrays: allocation-guard safe)
__device__ float g_q[TOK*DK];
__device__ float g_k[TOK*DK];
__device__ float g_v[TOK*DK];

// ---------------------------------------------------------------------------
// Kernel 1: fused QKV projection (unchanged from passing baseline).
// ---------------------------------------------------------------------------
#define KT 32

__global__ __launch_bounds__(256) void qkv_kernel(
    const float* __restrict__ x,
    const float* __restrict__ wq, const float* __restrict__ bq,
    const float* __restrict__ wk, const float* __restrict__ bk,
    const float* __restrict__ wv, const float* __restrict__ bv)
{
    __shared__ float Ash[KT][68];
    __shared__ float Bsh[KT][68];

    const int m0  = blockIdx.x * 64;
    const int sel = blockIdx.y;
    const float* w    = (sel == 0) ? wq : (sel == 1) ? wk : wv;
    const float* bias = (sel == 0) ? bq : (sel == 1) ? bk : bv;
    float* out        = (sel == 0) ? g_q : (sel == 1) ? g_k : g_v;

    const int t  = threadIdx.x;
    const int tx = t & 15;
    const int ty = t >> 4;
    const int lk  = t & 31;
    const int lr0 = t >> 5;

    float acc[4][4] = {};

    for (int k0 = 0; k0 < DM; k0 += KT) {
        __syncthreads();
        #pragma unroll
        for (int j = 0; j < 8; j++) {
            int r = lr0 + j * 8;
            Ash[lk][r] = x[(size_t)(m0 + r) * DM + k0 + lk];
        }
        #pragma unroll
        for (int j = 0; j < 8; j++) {
            int d = lr0 + j * 8;
            Bsh[lk][d] = w[(size_t)d * DM + k0 + lk];
        }
        __syncthreads();
        #pragma unroll
        for (int k = 0; k < KT; k++) {
            float4 a4 = *(const float4*)&Ash[k][ty * 4];
            float4 b4 = *(const float4*)&Bsh[k][tx * 4];
            float av[4] = {a4.x, a4.y, a4.z, a4.w};
            float bvv[4] = {b4.x, b4.y, b4.z, b4.w};
            #pragma unroll
            for (int i = 0; i < 4; i++)
                #pragma unroll
                for (int j = 0; j < 4; j++)
                    acc[i][j] += av[i] * bvv[j];
        }
    }

    float4 bb = *(const float4*)&bias[tx * 4];
    float bias4[4] = {bb.x, bb.y, bb.z, bb.w};
    #pragma unroll
    for (int i = 0; i < 4; i++) {
        int r = ty * 4 + i;
        float4 res;
        res.x = acc[i][0] + bias4[0];
        res.y = acc[i][1] + bias4[1];
        res.z = acc[i][2] + bias4[2];
        res.w = acc[i][3] + bias4[3];
        *(float4*)&out[(size_t)(m0 + r) * DK + tx * 4] = res;
    }
}

// ---------------------------------------------------------------------------
// Kernel 2: causal flash attention with tf32 mma.sync (m16n8k8).
// CTA = 128 threads = 4 warps; warp handles 16 q-rows x 64 k-cols.
// ---------------------------------------------------------------------------

__device__ __forceinline__ uint32_t f2tf(float f) {
    uint32_t r;
    asm("cvt.rna.tf32.f32 %0, %1;" : "=r"(r) : "f"(f));
    return r;
}

__device__ __forceinline__ void mma_tf32(float c[4],
                                         uint32_t a0, uint32_t a1, uint32_t a2, uint32_t a3,
                                         uint32_t b0, uint32_t b1) {
    asm volatile(
        "mma.sync.aligned.m16n8k8.row.col.f32.tf32.tf32.f32 "
        "{%0,%1,%2,%3}, {%4,%5,%6,%7}, {%8,%9}, {%0,%1,%2,%3};"
        : "+f"(c[0]), "+f"(c[1]), "+f"(c[2]), "+f"(c[3])
        : "r"(a0), "r"(a1), "r"(a2), "r"(a3), "r"(b0), "r"(b1));
}

// Balanced causal schedule: paired bids (s, s+148) sum to ~53 tiles;
// single-CTA SMs (108..147) get the largest tiles.
__device__ __forceinline__ void sched(int bid, int& b, int& qt) {
    int r;
    if (bid >= 108 && bid < 148)      r = bid - 108;
    else if (bid < 108)               r = 40 + bid;
    else                              r = 403 - bid;
    b  = r & 3;
    qt = 63 - (r >> 2);
}

#define KSTR 68
#define VSTR 72

__global__ __launch_bounds__(128) void attn_kernel(float* __restrict__ out)
{
    __shared__ uint32_t Ksh[64 * KSTR];   // K tile [token][d], tf32 bits
    __shared__ uint32_t Vsh[64 * VSTR];   // V tile [token][d], tf32 bits

    int b, qt;
    sched(blockIdx.x, b, qt);

    const int tid  = threadIdx.x;
    const int w    = tid >> 5;        // warp 0..3
    const int lane = tid & 31;
    const int q4   = lane & 3;        // threadID_in_group
    const int g    = lane >> 2;       // groupID (row within 8)

    // Warp's q rows: [qt*64 + w*16 + g] and [.. + 8]
    const int rl0 = w * 16 + g;          // in-tile row (reg pair 0)
    const size_t rowg  = (size_t)qt * 64 + rl0;
    const size_t baseg  = ((size_t)b * SEQ + rowg) * DK;
    const size_t baseg8 = baseg + 8 * DK;

    // Q A-fragments: qa[dk][4], scaled by 1/sqrt(64)=0.125 (exact) then tf32.
    uint32_t qa[8][4];
    #pragma unroll
    for (int dk = 0; dk < 8; dk++) {
        const int c0 = dk * 8 + q4;
        qa[dk][0] = f2tf(0.125f * g_q[baseg  + c0]);
        qa[dk][1] = f2tf(0.125f * g_q[baseg8 + c0]);
        qa[dk][2] = f2tf(0.125f * g_q[baseg  + c0 + 4]);
        qa[dk][3] = f2tf(0.125f * g_q[baseg8 + c0 + 4]);
    }

    float O[8][4];
    #pragma unroll
    for (int i = 0; i < 8; i++)
        #pragma unroll
        for (int j = 0; j < 4; j++) O[i][j] = 0.f;
    float m0 = -1e30f, m1 = -1e30f;
    float l0 = 0.f,    l1 = 0.f;

    for (int kt = 0; kt <= qt; kt++) {
        __syncthreads();   // prior PV reads done
        const size_t kvbase = ((size_t)b * SEQ + kt * 64) * DK;
        #pragma unroll
        for (int it = 0; it < 32; it++) {
            const int idx = tid + it * 128;       // 0..4095
            const int c = idx >> 6, d = idx & 63;
            Ksh[c * KSTR + d] = f2tf(g_k[kvbase + idx]);
            Vsh[c * VSTR + d] = f2tf(g_v[kvbase + idx]);
        }
        __syncthreads();

        // ---- S = Q K^T via mma: s[nt] covers cols 8nt..8nt+7 ----
        float s[8][4];
        #pragma unroll
        for (int nt = 0; nt < 8; nt++) {
            s[nt][0] = s[nt][1] = s[nt][2] = s[nt][3] = 0.f;
            const int tok = 8 * nt + g;          // B col(n) = key token
            #pragma unroll
            for (int dk = 0; dk < 8; dk++) {
                const uint32_t b0 = Ksh[tok * KSTR + 8 * dk + q4];
                const uint32_t b1 = Ksh[tok * KSTR + 8 * dk + q4 + 4];
                mma_tf32(s[nt], qa[dk][0], qa[dk][1], qa[dk][2], qa[dk][3], b0, b1);
            }
        }

        // ---- causal mask on diagonal tile ----
        if (kt == qt) {
            #pragma unroll
            for (int nt = 0; nt < 8; nt++) {
                const int c0 = 8 * nt + 2 * q4;
                if (c0     > rl0)     s[nt][0] = -1e30f;
                if (c0 + 1 > rl0)     s[nt][1] = -1e30f;
                if (c0     > rl0 + 8) s[nt][2] = -1e30f;
                if (c0 + 1 > rl0 + 8) s[nt][3] = -1e30f;
            }
        }

        // ---- online softmax (two independent row-halves) ----
        float r0 = -1e30f, r1 = -1e30f;
        #pragma unroll
        for (int nt = 0; nt < 8; nt++) {
            r0 = fmaxf(r0, fmaxf(s[nt][0], s[nt][1]));
            r1 = fmaxf(r1, fmaxf(s[nt][2], s[nt][3]));
        }
        r0 = fmaxf(r0, __shfl_xor_sync(0xffffffffu, r0, 1));
        r0 = fmaxf(r0, __shfl_xor_sync(0xffffffffu, r0, 2));
        r1 = fmaxf(r1, __shfl_xor_sync(0xffffffffu, r1, 1));
        r1 = fmaxf(r1, __shfl_xor_sync(0xffffffffu, r1, 2));

        const float mn0 = fmaxf(m0, r0);
        const float mn1 = fmaxf(m1, r1);
        const float sc0 = __expf(m0 - mn0);
        const float sc1 = __expf(m1 - mn1);
        float sum0 = 0.f, sum1 = 0.f;
        #pragma unroll
        for (int nt = 0; nt < 8; nt++) {
            s[nt][0] = __expf(s[nt][0] - mn0);
            s[nt][1] = __expf(s[nt][1] - mn0);
            s[nt][2] = __expf(s[nt][2] - mn1);
            s[nt][3] = __expf(s[nt][3] - mn1);
            sum0 += s[nt][0] + s[nt][1];
            sum1 += s[nt][2] + s[nt][3];
        }
        sum0 += __shfl_xor_sync(0xffffffffu, sum0, 1);
        sum0 += __shfl_xor_sync(0xffffffffu, sum0, 2);
        sum1 += __shfl_xor_sync(0xffffffffu, sum1, 1);
        sum1 += __shfl_xor_sync(0xffffffffu, sum1, 2);
        l0 = l0 * sc0 + sum0;  m0 = mn0;
        l1 = l1 * sc1 + sum1;  m1 = mn1;
        #pragma unroll
        for (int nt = 0; nt < 8; nt++) {
            O[nt][0] *= sc0; O[nt][1] *= sc0;
            O[nt][2] *= sc1; O[nt][3] *= sc1;
        }

        // ---- P: C-layout -> A-layout via quad shfl, then tf32 ----
        // a0(col q4) from lane base|(q4>>1) slot q4&1; a2(col q4+4) from base|((q4>>1)+2)
        uint32_t pa[8][4];
        const int srcA = (lane & ~3) | (q4 >> 1);
        const int srcB = srcA + 2;
        const bool hi = (q4 & 1);
        #pragma unroll
        for (int ktt = 0; ktt < 8; ktt++) {
            float v00 = __shfl_sync(0xffffffffu, s[ktt][0], srcA);
            float v01 = __shfl_sync(0xffffffffu, s[ktt][1], srcA);
            float v20 = __shfl_sync(0xffffffffu, s[ktt][2], srcA);
            float v21 = __shfl_sync(0xffffffffu, s[ktt][3], srcA);
            float u00 = __shfl_sync(0xffffffffu, s[ktt][0], srcB);
            float u01 = __shfl_sync(0xffffffffu, s[ktt][1], srcB);
            float u20 = __shfl_sync(0xffffffffu, s[ktt][2], srcB);
            float u21 = __shfl_sync(0xffffffffu, s[ktt][3], srcB);
            pa[ktt][0] = f2tf(hi ? v01 : v00);   // (row g,   t=8ktt+q4)
            pa[ktt][1] = f2tf(hi ? v21 : v20);   // (row g+8, t=8ktt+q4)
            pa[ktt][2] = f2tf(hi ? u01 : u00);   // (row g,   t=8ktt+q4+4)
            pa[ktt][3] = f2tf(hi ? u21 : u20);   // (row g+8, t=8ktt+q4+4)
        }

        // ---- O += P V via mma: ndt over d-tiles, ktt over token-tiles ----
        #pragma unroll
        for (int ndt = 0; ndt < 8; ndt++) {
            const int dcol = 8 * ndt + g;        // B col(n) = head dim d
            #pragma unroll
            for (int ktt = 0; ktt < 8; ktt++) {
                const uint32_t b0 = Vsh[(8 * ktt + q4)     * VSTR + dcol];
                const uint32_t b1 = Vsh[(8 * ktt + q4 + 4) * VSTR + dcol];
                mma_tf32(O[ndt], pa[ktt][0], pa[ktt][1], pa[ktt][2], pa[ktt][3], b0, b1);
            }
        }
    }

    // ---- normalize + store ----
    const float inv0 = 1.f / l0;
    const float inv1 = 1.f / l1;
    #pragma unroll
    for (int nt = 0; nt < 8; nt++) {
        const int d = 8 * nt + 2 * q4;
        float2 lo = make_float2(O[nt][0] * inv0, O[nt][1] * inv0);
        float2 hi2 = make_float2(O[nt][2] * inv1, O[nt][3] * inv1);
        *(float2*)&out[baseg  + d] = lo;
        *(float2*)&out[baseg8 + d] = hi2;
    }
}

// ---------------------------------------------------------------------------
extern "C" void kernel_launch(void* const* d_in, const int* in_sizes, int n_in,
                              void* d_out, int out_size) {
    (void)in_sizes; (void)n_in; (void)out_size;
    const float* x  = (const float*)d_in[0];
    const float* wq = (const float*)d_in[1];
    const float* bq = (const float*)d_in[2];
    const float* wk = (const float*)d_in[3];
    const float* bk = (const float*)d_in[4];
    const float* wv = (const float*)d_in[5];
    const float* bv = (const float*)d_in[6];
    float* out = (float*)d_out;

    qkv_kernel<<<dim3(TOK / 64, 3), 256>>>(x, wq, bq, wk, bk, wv, bv);
    attn_kernel<<<256, 128>>>(out);
}

// round 8
// speedup vs baseline: 9.0304x; 3.6845x over previous
#include <cuda_runtime.h>
#include <cuda_fp16.h>
#include <math.h>
#include <stdint.h>

#define BATCH 4
#define SEQ   4096
#define DM    1024
#define DK    64
#define TOK   (BATCH*SEQ)

// Projected q,k,v in fp16 (q pre-scaled by 1/sqrt(64))
__device__ __half g_q[TOK*DK];
__device__ __half g_k[TOK*DK];
__device__ __half g_v[TOK*DK];

__device__ __forceinline__ uint32_t smem_u32(const void* p) {
    return (uint32_t)__cvta_generic_to_shared(p);
}
__device__ __forceinline__ uint32_t h2pack(float lo, float hi) {
    __half2 h = __floats2half2_rn(lo, hi);
    return *(uint32_t*)&h;
}
__device__ __forceinline__ void ldsm4(uint32_t& r0, uint32_t& r1, uint32_t& r2, uint32_t& r3,
                                      uint32_t addr) {
    asm volatile("ldmatrix.sync.aligned.m8n8.x4.shared.b16 {%0,%1,%2,%3}, [%4];"
                 : "=r"(r0), "=r"(r1), "=r"(r2), "=r"(r3) : "r"(addr));
}
__device__ __forceinline__ void ldsm4t(uint32_t& r0, uint32_t& r1, uint32_t& r2, uint32_t& r3,
                                       uint32_t addr) {
    asm volatile("ldmatrix.sync.aligned.m8n8.x4.trans.shared.b16 {%0,%1,%2,%3}, [%4];"
                 : "=r"(r0), "=r"(r1), "=r"(r2), "=r"(r3) : "r"(addr));
}
__device__ __forceinline__ void mma_f16(float c[4],
                                        uint32_t a0, uint32_t a1, uint32_t a2, uint32_t a3,
                                        uint32_t b0, uint32_t b1) {
    asm volatile(
        "mma.sync.aligned.m16n8k16.row.col.f32.f16.f16.f32 "
        "{%0,%1,%2,%3}, {%4,%5,%6,%7}, {%8,%9}, {%0,%1,%2,%3};"
        : "+f"(c[0]), "+f"(c[1]), "+f"(c[2]), "+f"(c[3])
        : "r"(a0), "r"(a1), "r"(a2), "r"(a3), "r"(b0), "r"(b1));
}

// ---------------------------------------------------------------------------
// Kernel 1: fused QKV projection, fp16 mma. CTA: 64 rows x 192 cols (q|k|v).
// 256 threads = 8 warps (4 row-warps x 2 col-warps); warp tile 16 x 96.
// ---------------------------------------------------------------------------
#define XSTR 72
__global__ __launch_bounds__(256, 2) void qkv_kernel(
    const float* __restrict__ x,
    const float* __restrict__ wq, const float* __restrict__ bq,
    const float* __restrict__ wk, const float* __restrict__ bk,
    const float* __restrict__ wv, const float* __restrict__ bv)
{
    __shared__ __half Xs[64 * XSTR];     // x chunk  [row][k]
    __shared__ __half Ws[192 * XSTR];    // w chunk  [outcol][k]

    const int m0   = blockIdx.x * 64;
    const int tid  = threadIdx.x;
    const int wid  = tid >> 5;
    const int lane = tid & 31;
    const int g    = lane >> 2;
    const int q4   = lane & 3;
    const int warpRow = wid >> 1;        // 0..3
    const int warpCol = wid & 1;         // 0..1

    const uint32_t Xbase = smem_u32(Xs);
    const uint32_t Wbase = smem_u32(Ws);

    float c[12][4];
    #pragma unroll
    for (int i = 0; i < 12; i++)
        #pragma unroll
        for (int j = 0; j < 4; j++) c[i][j] = 0.f;

    for (int kc = 0; kc < 16; kc++) {
        const int k0 = kc * 64;
        __syncthreads();
        // stage x: 64x64 f32 -> fp16
        #pragma unroll
        for (int it = 0; it < 4; it++) {
            const int idx = tid + it * 256;          // 0..1023 float4 groups
            const int row = idx >> 4, c4 = (idx & 15) * 4;
            float4 v = *(const float4*)&x[(size_t)(m0 + row) * DM + k0 + c4];
            uint2 p;
            p.x = h2pack(v.x, v.y);
            p.y = h2pack(v.z, v.w);
            *(uint2*)&Xs[row * XSTR + c4] = p;
        }
        // stage w: 192x64 f32 -> fp16 (rows: 0-63 wq, 64-127 wk, 128-191 wv)
        #pragma unroll
        for (int it = 0; it < 12; it++) {
            const int idx = tid + it * 256;          // 0..3071
            const int row = idx >> 4, c4 = (idx & 15) * 4;
            const int sel = row >> 6, d = row & 63;
            const float* wp = (sel == 0) ? wq : (sel == 1) ? wk : wv;
            float4 v = *(const float4*)&wp[(size_t)d * DM + k0 + c4];
            uint2 p;
            p.x = h2pack(v.x, v.y);
            p.y = h2pack(v.z, v.w);
            *(uint2*)&Ws[row * XSTR + c4] = p;
        }
        __syncthreads();

        // A fragments: 4 k16-chunks of this warp's 16 rows
        uint32_t a[4][4];
        #pragma unroll
        for (int kk = 0; kk < 4; kk++) {
            const int row = warpRow * 16 + (lane & 7) + ((lane >> 3) & 1) * 8;
            const int col = 16 * kk + (lane >> 4) * 8;
            ldsm4(a[kk][0], a[kk][1], a[kk][2], a[kk][3],
                  Xbase + (row * XSTR + col) * 2);
        }
        // B fragments + mma
        #pragma unroll
        for (int nt = 0; nt < 12; nt++) {
            const int wrow = warpCol * 96 + 8 * nt + (lane & 7);
            uint32_t b0, b1, b2, b3, b4, b5, b6, b7;
            ldsm4(b0, b1, b2, b3, Wbase + (wrow * XSTR + 8 * (lane >> 3)) * 2);
            ldsm4(b4, b5, b6, b7, Wbase + (wrow * XSTR + 32 + 8 * (lane >> 3)) * 2);
            mma_f16(c[nt], a[0][0], a[0][1], a[0][2], a[0][3], b0, b1);
            mma_f16(c[nt], a[1][0], a[1][1], a[1][2], a[1][3], b2, b3);
            mma_f16(c[nt], a[2][0], a[2][1], a[2][2], a[2][3], b4, b5);
            mma_f16(c[nt], a[3][0], a[3][1], a[3][2], a[3][3], b6, b7);
        }
    }

    // epilogue: bias, (scale q), store fp16
    #pragma unroll
    for (int nt = 0; nt < 12; nt++) {
        const int dcol = warpCol * 96 + 8 * nt + 2 * q4;
        const int sel = dcol >> 6, within = dcol & 63;
        const float* bp = (sel == 0) ? bq : (sel == 1) ? bk : bv;
        __half* op      = (sel == 0) ? g_q : (sel == 1) ? g_k : g_v;
        const float b0 = bp[within], b1 = bp[within + 1];
        const float sc = (sel == 0) ? 0.125f : 1.0f;
        const int r0 = m0 + warpRow * 16 + g;
        *(uint32_t*)&op[(size_t)r0 * DK + within] =
            h2pack(sc * (c[nt][0] + b0), sc * (c[nt][1] + b1));
        *(uint32_t*)&op[(size_t)(r0 + 8) * DK + within] =
            h2pack(sc * (c[nt][2] + b0), sc * (c[nt][3] + b1));
    }
}

// ---------------------------------------------------------------------------
// Kernel 2: causal flash attention, fp16 mma m16n8k16.
// CTA = 128 threads = 4 warps; warp = 16 q-rows x 64 k-cols.
// ---------------------------------------------------------------------------
__device__ __forceinline__ void sched(int bid, int& b, int& qt) {
    int r;
    if (bid >= 108 && bid < 148)      r = bid - 108;
    else if (bid < 108)               r = 40 + bid;
    else                              r = 403 - bid;
    b  = r & 3;
    qt = 63 - (r >> 2);
}

#define KSTR 72
__global__ __launch_bounds__(128, 2) void attn_kernel(float* __restrict__ out)
{
    __shared__ __half Ksh[64 * KSTR];
    __shared__ __half Vsh[64 * KSTR];

    int b, qt;
    sched(blockIdx.x, b, qt);

    const int tid  = threadIdx.x;
    const int w    = tid >> 5;
    const int lane = tid & 31;
    const int q4   = lane & 3;
    const int g    = lane >> 2;

    const uint32_t Kbase = smem_u32(Ksh);
    const uint32_t Vbase = smem_u32(Vsh);

    const int rl0 = w * 16 + g;
    const size_t rowg   = (size_t)qt * 64 + rl0;
    const size_t baseg  = ((size_t)b * SEQ + rowg) * DK;
    const size_t baseg8 = baseg + 8 * DK;

    // Q A-fragments (q already scaled by 0.125 in projection)
    uint32_t qa[4][4];
    #pragma unroll
    for (int kk = 0; kk < 4; kk++) {
        const int col = 16 * kk + 2 * q4;
        qa[kk][0] = *(const uint32_t*)&g_q[baseg  + col];
        qa[kk][1] = *(const uint32_t*)&g_q[baseg8 + col];
        qa[kk][2] = *(const uint32_t*)&g_q[baseg  + col + 8];
        qa[kk][3] = *(const uint32_t*)&g_q[baseg8 + col + 8];
    }

    float O[8][4];
    #pragma unroll
    for (int i = 0; i < 8; i++)
        #pragma unroll
        for (int j = 0; j < 4; j++) O[i][j] = 0.f;
    float m0 = -1e30f, m1 = -1e30f;
    float l0 = 0.f,    l1 = 0.f;

    for (int kt = 0; kt <= qt; kt++) {
        __syncthreads();
        const size_t kvbase = ((size_t)b * SEQ + kt * 64) * DK;
        // stage K,V fp16: pure uint4 copies, swizzle-free layout (stride 72)
        #pragma unroll
        for (int it = 0; it < 4; it++) {
            const int idx = tid + it * 128;         // 0..511 uint4 groups
            const int row = idx >> 3, u = (idx & 7) * 8;
            *(uint4*)&Ksh[row * KSTR + u] = *(const uint4*)&g_k[kvbase + idx * 8];
            *(uint4*)&Vsh[row * KSTR + u] = *(const uint4*)&g_v[kvbase + idx * 8];
        }
        __syncthreads();

        // ---- S = Q K^T ----
        float s[8][4];
        #pragma unroll
        for (int nt = 0; nt < 8; nt++) {
            s[nt][0] = s[nt][1] = s[nt][2] = s[nt][3] = 0.f;
            const int row = 8 * nt + (lane & 7);
            uint32_t b0, b1, b2, b3, b4, b5, b6, b7;
            ldsm4(b0, b1, b2, b3, Kbase + (row * KSTR + 8 * (lane >> 3)) * 2);
            ldsm4(b4, b5, b6, b7, Kbase + (row * KSTR + 32 + 8 * (lane >> 3)) * 2);
            mma_f16(s[nt], qa[0][0], qa[0][1], qa[0][2], qa[0][3], b0, b1);
            mma_f16(s[nt], qa[1][0], qa[1][1], qa[1][2], qa[1][3], b2, b3);
            mma_f16(s[nt], qa[2][0], qa[2][1], qa[2][2], qa[2][3], b4, b5);
            mma_f16(s[nt], qa[3][0], qa[3][1], qa[3][2], qa[3][3], b6, b7);
        }

        // causal mask on diagonal tile
        if (kt == qt) {
            #pragma unroll
            for (int nt = 0; nt < 8; nt++) {
                const int c0 = 8 * nt + 2 * q4;
                if (c0     > rl0)     s[nt][0] = -1e30f;
                if (c0 + 1 > rl0)     s[nt][1] = -1e30f;
                if (c0     > rl0 + 8) s[nt][2] = -1e30f;
                if (c0 + 1 > rl0 + 8) s[nt][3] = -1e30f;
            }
        }

        // ---- online softmax ----
        float r0 = -1e30f, r1 = -1e30f;
        #pragma unroll
        for (int nt = 0; nt < 8; nt++) {
            r0 = fmaxf(r0, fmaxf(s[nt][0], s[nt][1]));
            r1 = fmaxf(r1, fmaxf(s[nt][2], s[nt][3]));
        }
        r0 = fmaxf(r0, __shfl_xor_sync(0xffffffffu, r0, 1));
        r0 = fmaxf(r0, __shfl_xor_sync(0xffffffffu, r0, 2));
        r1 = fmaxf(r1, __shfl_xor_sync(0xffffffffu, r1, 1));
        r1 = fmaxf(r1, __shfl_xor_sync(0xffffffffu, r1, 2));
        const float mn0 = fmaxf(m0, r0);
        const float mn1 = fmaxf(m1, r1);
        const float sc0 = __expf(m0 - mn0);
        const float sc1 = __expf(m1 - mn1);
        float sum0 = 0.f, sum1 = 0.f;
        #pragma unroll
        for (int nt = 0; nt < 8; nt++) {
            s[nt][0] = __expf(s[nt][0] - mn0);
            s[nt][1] = __expf(s[nt][1] - mn0);
            s[nt][2] = __expf(s[nt][2] - mn1);
            s[nt][3] = __expf(s[nt][3] - mn1);
            sum0 += s[nt][0] + s[nt][1];
            sum1 += s[nt][2] + s[nt][3];
        }
        sum0 += __shfl_xor_sync(0xffffffffu, sum0, 1);
        sum0 += __shfl_xor_sync(0xffffffffu, sum0, 2);
        sum1 += __shfl_xor_sync(0xffffffffu, sum1, 1);
        sum1 += __shfl_xor_sync(0xffffffffu, sum1, 2);
        l0 = l0 * sc0 + sum0;  m0 = mn0;
        l1 = l1 * sc1 + sum1;  m1 = mn1;
        #pragma unroll
        for (int nt = 0; nt < 8; nt++) {
            O[nt][0] *= sc0; O[nt][1] *= sc0;
            O[nt][2] *= sc1; O[nt][3] *= sc1;
        }

        // ---- P C-layout -> fp16 A-fragments (pure register packs) ----
        uint32_t pa[4][4];
        #pragma unroll
        for (int ktt = 0; ktt < 4; ktt++) {
            pa[ktt][0] = h2pack(s[2 * ktt][0],     s[2 * ktt][1]);
            pa[ktt][1] = h2pack(s[2 * ktt][2],     s[2 * ktt][3]);
            pa[ktt][2] = h2pack(s[2 * ktt + 1][0], s[2 * ktt + 1][1]);
            pa[ktt][3] = h2pack(s[2 * ktt + 1][2], s[2 * ktt + 1][3]);
        }

        // ---- O += P V ----
        #pragma unroll
        for (int ktt = 0; ktt < 4; ktt++) {
            const int t = lane >> 3, l = lane & 7;
            const int vrow = 16 * ktt + (t & 1) * 8 + l;
            #pragma unroll
            for (int nd = 0; nd < 4; nd++) {        // ndt pairs: (2nd, 2nd+1)
                const int col = 16 * nd + (t >> 1) * 8;
                uint32_t b0, b1, b2, b3;
                ldsm4t(b0, b1, b2, b3, Vbase + (vrow * KSTR + col) * 2);
                mma_f16(O[2 * nd],     pa[ktt][0], pa[ktt][1], pa[ktt][2], pa[ktt][3], b0, b1);
                mma_f16(O[2 * nd + 1], pa[ktt][0], pa[ktt][1], pa[ktt][2], pa[ktt][3], b2, b3);
            }
        }
    }

    const float inv0 = 1.f / l0;
    const float inv1 = 1.f / l1;
    #pragma unroll
    for (int nt = 0; nt < 8; nt++) {
        const int d = 8 * nt + 2 * q4;
        *(float2*)&out[baseg  + d] = make_float2(O[nt][0] * inv0, O[nt][1] * inv0);
        *(float2*)&out[baseg8 + d] = make_float2(O[nt][2] * inv1, O[nt][3] * inv1);
    }
}

// ---------------------------------------------------------------------------
extern "C" void kernel_launch(void* const* d_in, const int* in_sizes, int n_in,
                              void* d_out, int out_size) {
    (void)in_sizes; (void)n_in; (void)out_size;
    const float* x  = (const float*)d_in[0];
    const float* wq = (const float*)d_in[1];
    const float* bq = (const float*)d_in[2];
    const float* wk = (const float*)d_in[3];
    const float* bk = (const float*)d_in[4];
    const float* wv = (const float*)d_in[5];
    const float* bv = (const float*)d_in[6];
    float* out = (float*)d_out;

    qkv_kernel<<<256, 256>>>(x, wq, bq, wk, bk, wv, bv);
    attn_kernel<<<256, 128>>>(out);
}

// round 11
// speedup vs baseline: 10.8691x; 1.2036x over previous
#include <cuda_runtime.h>
#include <cuda_fp16.h>
#include <math.h>
#include <stdint.h>

#define BATCH 4
#define SEQ   4096
#define DM    1024
#define DK    64
#define TOK   (BATCH*SEQ)

// Projected q,k,v in fp16 (q pre-scaled by 1/sqrt(64))
__device__ __half g_q[TOK*DK];
__device__ __half g_k[TOK*DK];
__device__ __half g_v[TOK*DK];

// Split-K partial results (unnormalized O, running max m, running sum l)
__device__ float g_po[2][TOK*DK];
__device__ float g_pm[2][TOK];
__device__ float g_pl[2][TOK];

__device__ __forceinline__ uint32_t smem_u32(const void* p) {
    return (uint32_t)__cvta_generic_to_shared(p);
}
__device__ __forceinline__ uint32_t h2pack(float lo, float hi) {
    __half2 h = __floats2half2_rn(lo, hi);
    return *(uint32_t*)&h;
}
__device__ __forceinline__ void ldsm4(uint32_t& r0, uint32_t& r1, uint32_t& r2, uint32_t& r3,
                                      uint32_t addr) {
    asm volatile("ldmatrix.sync.aligned.m8n8.x4.shared.b16 {%0,%1,%2,%3}, [%4];"
                 : "=r"(r0), "=r"(r1), "=r"(r2), "=r"(r3) : "r"(addr));
}
__device__ __forceinline__ void ldsm4t(uint32_t& r0, uint32_t& r1, uint32_t& r2, uint32_t& r3,
                                       uint32_t addr) {
    asm volatile("ldmatrix.sync.aligned.m8n8.x4.trans.shared.b16 {%0,%1,%2,%3}, [%4];"
                 : "=r"(r0), "=r"(r1), "=r"(r2), "=r"(r3) : "r"(addr));
}
__device__ __forceinline__ void mma_f16(float c[4],
                                        uint32_t a0, uint32_t a1, uint32_t a2, uint32_t a3,
                                        uint32_t b0, uint32_t b1) {
    asm volatile(
        "mma.sync.aligned.m16n8k16.row.col.f32.f16.f16.f32 "
        "{%0,%1,%2,%3}, {%4,%5,%6,%7}, {%8,%9}, {%0,%1,%2,%3};"
        : "+f"(c[0]), "+f"(c[1]), "+f"(c[2]), "+f"(c[3])
        : "r"(a0), "r"(a1), "r"(a2), "r"(a3), "r"(b0), "r"(b1));
}

// ---------------------------------------------------------------------------
// Kernel 1: fused QKV projection, fp16 mma (unchanged; measured ~25us).
// ---------------------------------------------------------------------------
#define XSTR 72
__global__ __launch_bounds__(256, 2) void qkv_kernel(
    const float* __restrict__ x,
    const float* __restrict__ wq, const float* __restrict__ bq,
    const float* __restrict__ wk, const float* __restrict__ bk,
    const float* __restrict__ wv, const float* __restrict__ bv)
{
    __shared__ __half Xs[64 * XSTR];     // x chunk  [row][k]
    __shared__ __half Ws[192 * XSTR];    // w chunk  [outcol][k]

    const int m0   = blockIdx.x * 64;
    const int tid  = threadIdx.x;
    const int wid  = tid >> 5;
    const int lane = tid & 31;
    const int g    = lane >> 2;
    const int q4   = lane & 3;
    const int warpRow = wid >> 1;        // 0..3
    const int warpCol = wid & 1;         // 0..1

    const uint32_t Xbase = smem_u32(Xs);
    const uint32_t Wbase = smem_u32(Ws);

    float c[12][4];
    #pragma unroll
    for (int i = 0; i < 12; i++)
        #pragma unroll
        for (int j = 0; j < 4; j++) c[i][j] = 0.f;

    for (int kc = 0; kc < 16; kc++) {
        const int k0 = kc * 64;
        __syncthreads();
        #pragma unroll
        for (int it = 0; it < 4; it++) {
            const int idx = tid + it * 256;
            const int row = idx >> 4, c4 = (idx & 15) * 4;
            float4 v = *(const float4*)&x[(size_t)(m0 + row) * DM + k0 + c4];
            uint2 p;
            p.x = h2pack(v.x, v.y);
            p.y = h2pack(v.z, v.w);
            *(uint2*)&Xs[row * XSTR + c4] = p;
        }
        #pragma unroll
        for (int it = 0; it < 12; it++) {
            const int idx = tid + it * 256;
            const int row = idx >> 4, c4 = (idx & 15) * 4;
            const int sel = row >> 6, d = row & 63;
            const float* wp = (sel == 0) ? wq : (sel == 1) ? wk : wv;
            float4 v = *(const float4*)&wp[(size_t)d * DM + k0 + c4];
            uint2 p;
            p.x = h2pack(v.x, v.y);
            p.y = h2pack(v.z, v.w);
            *(uint2*)&Ws[row * XSTR + c4] = p;
        }
        __syncthreads();

        uint32_t a[4][4];
        #pragma unroll
        for (int kk = 0; kk < 4; kk++) {
            const int row = warpRow * 16 + (lane & 7) + ((lane >> 3) & 1) * 8;
            const int col = 16 * kk + (lane >> 4) * 8;
            ldsm4(a[kk][0], a[kk][1], a[kk][2], a[kk][3],
                  Xbase + (row * XSTR + col) * 2);
        }
        #pragma unroll
        for (int nt = 0; nt < 12; nt++) {
            const int wrow = warpCol * 96 + 8 * nt + (lane & 7);
            uint32_t b0, b1, b2, b3, b4, b5, b6, b7;
            ldsm4(b0, b1, b2, b3, Wbase + (wrow * XSTR + 8 * (lane >> 3)) * 2);
            ldsm4(b4, b5, b6, b7, Wbase + (wrow * XSTR + 32 + 8 * (lane >> 3)) * 2);
            mma_f16(c[nt], a[0][0], a[0][1], a[0][2], a[0][3], b0, b1);
            mma_f16(c[nt], a[1][0], a[1][1], a[1][2], a[1][3], b2, b3);
            mma_f16(c[nt], a[2][0], a[2][1], a[2][2], a[2][3], b4, b5);
            mma_f16(c[nt], a[3][0], a[3][1], a[3][2], a[3][3], b6, b7);
        }
    }

    #pragma unroll
    for (int nt = 0; nt < 12; nt++) {
        const int dcol = warpCol * 96 + 8 * nt + 2 * q4;
        const int sel = dcol >> 6, within = dcol & 63;
        const float* bp = (sel == 0) ? bq : (sel == 1) ? bk : bv;
        __half* op      = (sel == 0) ? g_q : (sel == 1) ? g_k : g_v;
        const float b0 = bp[within], b1 = bp[within + 1];
        const float sc = (sel == 0) ? 0.125f : 1.0f;
        const int r0 = m0 + warpRow * 16 + g;
        *(uint32_t*)&op[(size_t)r0 * DK + within] =
            h2pack(sc * (c[nt][0] + b0), sc * (c[nt][1] + b1));
        *(uint32_t*)&op[(size_t)(r0 + 8) * DK + within] =
            h2pack(sc * (c[nt][2] + b0), sc * (c[nt][3] + b1));
    }
}

// ---------------------------------------------------------------------------
// Kernel 2: split-K causal flash attention partials, fp16 mma m16n8k16.
// Grid = 512: bid -> (qt descending for largest-first scheduling, parity, batch).
// CTA (128 thr, 4 warps) processes K-tiles kt = p, p+2, ... <= qt and writes
// unnormalized O plus (m, l) per row.
// ---------------------------------------------------------------------------
#define KSTR 72
__global__ __launch_bounds__(128, 2) void attn_partial_kernel()
{
    __shared__ __half Ksh[64 * KSTR];
    __shared__ __half Vsh[64 * KSTR];

    const int bid = blockIdx.x;
    const int qt  = 63 - (bid >> 3);     // largest q-tiles launch first
    const int b   = bid & 3;
    const int p   = (bid >> 2) & 1;      // K-tile parity handled by this CTA

    const int tid  = threadIdx.x;
    const int w    = tid >> 5;
    const int lane = tid & 31;
    const int q4   = lane & 3;
    const int g    = lane >> 2;

    const uint32_t Kbase = smem_u32(Ksh);
    const uint32_t Vbase = smem_u32(Vsh);

    const int rl0 = w * 16 + g;
    const size_t row0   = (size_t)b * SEQ + (size_t)qt * 64 + rl0;  // abs token
    const size_t baseg  = row0 * DK;
    const size_t baseg8 = baseg + 8 * DK;

    // Q A-fragments (q already scaled by 0.125 in projection)
    uint32_t qa[4][4];
    #pragma unroll
    for (int kk = 0; kk < 4; kk++) {
        const int col = 16 * kk + 2 * q4;
        qa[kk][0] = *(const uint32_t*)&g_q[baseg  + col];
        qa[kk][1] = *(const uint32_t*)&g_q[baseg8 + col];
        qa[kk][2] = *(const uint32_t*)&g_q[baseg  + col + 8];
        qa[kk][3] = *(const uint32_t*)&g_q[baseg8 + col + 8];
    }

    float O[8][4];
    #pragma unroll
    for (int i = 0; i < 8; i++)
        #pragma unroll
        for (int j = 0; j < 4; j++) O[i][j] = 0.f;
    float m0 = -1e30f, m1 = -1e30f;
    float l0 = 0.f,    l1 = 0.f;

    for (int kt = p; kt <= qt; kt += 2) {
        __syncthreads();
        const size_t kvbase = ((size_t)b * SEQ + kt * 64) * DK;
        #pragma unroll
        for (int it = 0; it < 4; it++) {
            const int idx = tid + it * 128;
            const int row = idx >> 3, u = (idx & 7) * 8;
            *(uint4*)&Ksh[row * KSTR + u] = *(const uint4*)&g_k[kvbase + idx * 8];
            *(uint4*)&Vsh[row * KSTR + u] = *(const uint4*)&g_v[kvbase + idx * 8];
        }
        __syncthreads();

        // ---- S = Q K^T ----
        float s[8][4];
        #pragma unroll
        for (int nt = 0; nt < 8; nt++) {
            s[nt][0] = s[nt][1] = s[nt][2] = s[nt][3] = 0.f;
            const int row = 8 * nt + (lane & 7);
            uint32_t b0, b1, b2, b3, b4, b5, b6, b7;
            ldsm4(b0, b1, b2, b3, Kbase + (row * KSTR + 8 * (lane >> 3)) * 2);
            ldsm4(b4, b5, b6, b7, Kbase + (row * KSTR + 32 + 8 * (lane >> 3)) * 2);
            mma_f16(s[nt], qa[0][0], qa[0][1], qa[0][2], qa[0][3], b0, b1);
            mma_f16(s[nt], qa[1][0], qa[1][1], qa[1][2], qa[1][3], b2, b3);
            mma_f16(s[nt], qa[2][0], qa[2][1], qa[2][2], qa[2][3], b4, b5);
            mma_f16(s[nt], qa[3][0], qa[3][1], qa[3][2], qa[3][3], b6, b7);
        }

        // causal mask on diagonal tile (only reached when qt%2 == p)
        if (kt == qt) {
            #pragma unroll
            for (int nt = 0; nt < 8; nt++) {
                const int c0 = 8 * nt + 2 * q4;
                if (c0     > rl0)     s[nt][0] = -1e30f;
                if (c0 + 1 > rl0)     s[nt][1] = -1e30f;
                if (c0     > rl0 + 8) s[nt][2] = -1e30f;
                if (c0 + 1 > rl0 + 8) s[nt][3] = -1e30f;
            }
        }

        // ---- online softmax ----
        float r0 = -1e30f, r1 = -1e30f;
        #pragma unroll
        for (int nt = 0; nt < 8; nt++) {
            r0 = fmaxf(r0, fmaxf(s[nt][0], s[nt][1]));
            r1 = fmaxf(r1, fmaxf(s[nt][2], s[nt][3]));
        }
        r0 = fmaxf(r0, __shfl_xor_sync(0xffffffffu, r0, 1));
        r0 = fmaxf(r0, __shfl_xor_sync(0xffffffffu, r0, 2));
        r1 = fmaxf(r1, __shfl_xor_sync(0xffffffffu, r1, 1));
        r1 = fmaxf(r1, __shfl_xor_sync(0xffffffffu, r1, 2));
        const float mn0 = fmaxf(m0, r0);
        const float mn1 = fmaxf(m1, r1);
        const float sc0 = __expf(m0 - mn0);
        const float sc1 = __expf(m1 - mn1);
        float sum0 = 0.f, sum1 = 0.f;
        #pragma unroll
        for (int nt = 0; nt < 8; nt++) {
            s[nt][0] = __expf(s[nt][0] - mn0);
            s[nt][1] = __expf(s[nt][1] - mn0);
            s[nt][2] = __expf(s[nt][2] - mn1);
            s[nt][3] = __expf(s[nt][3] - mn1);
            sum0 += s[nt][0] + s[nt][1];
            sum1 += s[nt][2] + s[nt][3];
        }
        sum0 += __shfl_xor_sync(0xffffffffu, sum0, 1);
        sum0 += __shfl_xor_sync(0xffffffffu, sum0, 2);
        sum1 += __shfl_xor_sync(0xffffffffu, sum1, 1);
        sum1 += __shfl_xor_sync(0xffffffffu, sum1, 2);
        l0 = l0 * sc0 + sum0;  m0 = mn0;
        l1 = l1 * sc1 + sum1;  m1 = mn1;
        #pragma unroll
        for (int nt = 0; nt < 8; nt++) {
            O[nt][0] *= sc0; O[nt][1] *= sc0;
            O[nt][2] *= sc1; O[nt][3] *= sc1;
        }

        // ---- P C-layout -> fp16 A-fragments (register packs) ----
        uint32_t pa[4][4];
        #pragma unroll
        for (int ktt = 0; ktt < 4; ktt++) {
            pa[ktt][0] = h2pack(s[2 * ktt][0],     s[2 * ktt][1]);
            pa[ktt][1] = h2pack(s[2 * ktt][2],     s[2 * ktt][3]);
            pa[ktt][2] = h2pack(s[2 * ktt + 1][0], s[2 * ktt + 1][1]);
            pa[ktt][3] = h2pack(s[2 * ktt + 1][2], s[2 * ktt + 1][3]);
        }

        // ---- O += P V ----
        #pragma unroll
        for (int ktt = 0; ktt < 4; ktt++) {
            const int t = lane >> 3, l = lane & 7;
            const int vrow = 16 * ktt + (t & 1) * 8 + l;
            #pragma unroll
            for (int nd = 0; nd < 4; nd++) {
                const int col = 16 * nd + (t >> 1) * 8;
                uint32_t b0, b1, b2, b3;
                ldsm4t(b0, b1, b2, b3, Vbase + (vrow * KSTR + col) * 2);
                mma_f16(O[2 * nd],     pa[ktt][0], pa[ktt][1], pa[ktt][2], pa[ktt][3], b0, b1);
                mma_f16(O[2 * nd + 1], pa[ktt][0], pa[ktt][1], pa[ktt][2], pa[ktt][3], b2, b3);
            }
        }
    }

    // ---- write unnormalized partials ----
    #pragma unroll
    for (int nt = 0; nt < 8; nt++) {
        const int d = 8 * nt + 2 * q4;
        *(float2*)&g_po[p][baseg  + d] = make_float2(O[nt][0], O[nt][1]);
        *(float2*)&g_po[p][baseg8 + d] = make_float2(O[nt][2], O[nt][3]);
    }
    if (q4 == 0) {
        g_pm[p][row0]     = m0;  g_pl[p][row0]     = l0;
        g_pm[p][row0 + 8] = m1;  g_pl[p][row0 + 8] = l1;
    }
}

// ---------------------------------------------------------------------------
// Kernel 3: merge the two split-K partials. Memory-bound, ~4us.
// Grid 1024 x 256 threads; block handles 16 rows x 64 cols (float4 per thread).
// ---------------------------------------------------------------------------
__global__ __launch_bounds__(256) void merge_kernel(float* __restrict__ out)
{
    const int t   = threadIdx.x;
    const int row = blockIdx.x * 16 + (t >> 4);
    const int c4  = (t & 15) * 4;

    const float ma = g_pm[0][row], mb = g_pm[1][row];
    const float la = g_pl[0][row], lb = g_pl[1][row];
    const float m  = fmaxf(ma, mb);
    const float sa = __expf(ma - m);
    const float sb = __expf(mb - m);
    const float inv = 1.f / (la * sa + lb * sb);

    const size_t base = (size_t)row * DK + c4;
    float4 oa = *(const float4*)&g_po[0][base];
    float4 ob = *(const float4*)&g_po[1][base];
    float4 r;
    r.x = (oa.x * sa + ob.x * sb) * inv;
    r.y = (oa.y * sa + ob.y * sb) * inv;
    r.z = (oa.z * sa + ob.z * sb) * inv;
    r.w = (oa.w * sa + ob.w * sb) * inv;
    *(float4*)&out[base] = r;
}

// ---------------------------------------------------------------------------
extern "C" void kernel_launch(void* const* d_in, const int* in_sizes, int n_in,
                              void* d_out, int out_size) {
    (void)in_sizes; (void)n_in; (void)out_size;
    const float* x  = (const float*)d_in[0];
    const float* wq = (const float*)d_in[1];
    const float* bq = (const float*)d_in[2];
    const float* wk = (const float*)d_in[3];
    const float* bk = (const float*)d_in[4];
    const float* wv = (const float*)d_in[5];
    const float* bv = (const float*)d_in[6];
    float* out = (float*)d_out;

    qkv_kernel<<<256, 256>>>(x, wq, bq, wk, bk, wv, bv);
    attn_partial_kernel<<<512, 128>>>();
    merge_kernel<<<1024, 256>>>(out);
}